// round 4
// baseline (speedup 1.0000x reference)
#include <cuda_runtime.h>
#include <cuda_bf16.h>
#include <cstdint>

#define BB 64      // batch
#define TT 512     // timesteps
#define DD 256     // input dim
#define HH 1024    // hidden
#define GG 4096    // 4*H

// ---------------- scratch (device-global; no allocs allowed) ----------------
__device__ __align__(16) __nv_bfloat16 g_A0h[(size_t)TT * BB * DD];   // x hi plane [t*B+b][D]
__device__ __align__(16) __nv_bfloat16 g_A0l[(size_t)TT * BB * DD];   // x lo plane
__device__ __align__(16) __nv_bfloat16 g_wbh[(size_t)GG * HH];        // w_ih hi
__device__ __align__(16) __nv_bfloat16 g_wbl[(size_t)GG * HH];        // w_ih lo
__device__ __align__(16) __nv_bfloat16 g_whh_lo[(size_t)GG * HH];     // w_hh lo plane
__device__ __align__(16) float         g_xp[(size_t)TT * BB * GG];    // projections + biases
__device__ __align__(16) __nv_bfloat16 g_hseq_h[(size_t)TT * BB * HH];
__device__ __align__(16) __nv_bfloat16 g_hseq_l[(size_t)TT * BB * HH];
__device__ __align__(16) __nv_bfloat16 g_hbuf_h[2][BB * HH];
__device__ __align__(16) __nv_bfloat16 g_hbuf_l[2][BB * HH];
__device__ unsigned g_arrive[TT];

// strides (words mod 32 == 4 -> conflict-free quad access)
#define RS_W 1032    // W_hi row stride (bf16): 1032*2/4=516 words, 516%32=4
#define RS_C 72      // chunk row stride (bf16): 36 words, %32=4
#define RS_G 68      // gate row stride (fp32)
#define NCH  16      // 1024/64 k-chunks
#define CH   64

#define OFF_WS   0
#define OFF_HH0  (64 * RS_W * 2)                       // 132096
#define OFF_HL0  (OFF_HH0 + 2 * 64 * RS_C * 2)        // + 18432
#define OFF_WL0  (OFF_HL0 + 2 * 64 * RS_C * 2)
#define OFF_GS   (OFF_WL0 + 2 * 64 * RS_C * 2)
#define OFF_CS   (OFF_GS + 64 * RS_G * 4)
#define SMEM_RECUR (OFF_CS + 1024 * 4)                // 208896 bytes

// ---------------- helpers ----------------
__device__ __forceinline__ void mma16816(float* c, uint32_t a0, uint32_t a1,
                                         uint32_t a2, uint32_t a3,
                                         uint32_t b0, uint32_t b1) {
    asm volatile(
        "mma.sync.aligned.m16n8k16.row.col.f32.bf16.bf16.f32 "
        "{%0,%1,%2,%3}, {%4,%5,%6,%7}, {%8,%9}, {%0,%1,%2,%3};"
        : "+f"(c[0]), "+f"(c[1]), "+f"(c[2]), "+f"(c[3])
        : "r"(a0), "r"(a1), "r"(a2), "r"(a3), "r"(b0), "r"(b1));
}
__device__ __forceinline__ void cp_async16(void* s, const void* g) {
    uint32_t sa = (uint32_t)__cvta_generic_to_shared(s);
    asm volatile("cp.async.cg.shared.global [%0], [%1], 16;\n" ::"r"(sa), "l"(g));
}
#define CP_COMMIT() asm volatile("cp.async.commit_group;\n")
#define CP_WAIT(N)  asm volatile("cp.async.wait_group %0;\n" ::"n"(N))

__device__ __forceinline__ float sigmoid_f(float x) { return 1.f / (1.f + __expf(-x)); }
__device__ __forceinline__ float tanh_f(float x) { return 2.f / (1.f + __expf(-2.f * x)) - 1.f; }

__device__ __forceinline__ void split_bf16(float v, __nv_bfloat16& hi, __nv_bfloat16& lo) {
    hi = __float2bfloat16(v);
    lo = __float2bfloat16(v - __bfloat162float(hi));
}

// ---------------- prep ----------------
__global__ void prep_kernel() {
    int idx = blockIdx.x * blockDim.x + threadIdx.x;
    int nh = 2 * BB * HH;
    int total = TT + 2 * nh;
    for (int i = idx; i < total; i += gridDim.x * blockDim.x) {
        if (i < TT) g_arrive[i] = 0u;
        else if (i < TT + nh) ((__nv_bfloat16*)g_hbuf_h)[i - TT] = __float2bfloat16(0.f);
        else ((__nv_bfloat16*)g_hbuf_l)[i - TT - nh] = __float2bfloat16(0.f);
    }
}

// x[B][T][D] fp32 -> split planes [t*B+b][D]
__global__ void convert_x_kernel(const float* __restrict__ x) {
    size_t total = (size_t)BB * TT * DD;
    for (size_t i = (size_t)blockIdx.x * blockDim.x + threadIdx.x; i < total;
         i += (size_t)gridDim.x * blockDim.x) {
        int b = (int)(i / (TT * DD));
        int r = (int)(i % (TT * DD));
        int t = r / DD, d = r % DD;
        __nv_bfloat16 hi, lo;
        split_bf16(x[i], hi, lo);
        size_t o = ((size_t)t * BB + b) * DD + d;
        g_A0h[o] = hi;
        g_A0l[o] = lo;
    }
}

__global__ void convert_wih_kernel(const float* __restrict__ w, int n) {
    for (int i = blockIdx.x * blockDim.x + threadIdx.x; i < n; i += gridDim.x * blockDim.x) {
        __nv_bfloat16 hi, lo;
        split_bf16(w[i], hi, lo);
        g_wbh[i] = hi;
        g_wbl[i] = lo;
    }
}

__global__ void convert_whh_lo_kernel(const float* __restrict__ w) {
    int n = GG * HH;
    for (int i = blockIdx.x * blockDim.x + threadIdx.x; i < n; i += gridDim.x * blockDim.x) {
        __nv_bfloat16 hi, lo;
        split_bf16(w[i], hi, lo);
        g_whh_lo[i] = lo;
    }
}

// ---------------- projection GEMM (bf16x3): C = A.Wt + b1 + b2 ----------------
// A planes [M][K], W planes [GG][K], C = g_xp [M][GG]. Tile 64x64, BK=64.
__global__ __launch_bounds__(256) void gemm_kernel(int layer, int K,
                                                   const float* __restrict__ bias1,
                                                   const float* __restrict__ bias2) {
    const __nv_bfloat16* Ah = (layer == 0) ? g_A0h : g_hseq_h;
    const __nv_bfloat16* Al = (layer == 0) ? g_A0l : g_hseq_l;
    __shared__ __nv_bfloat16 AsH[64][RS_C], AsL[64][RS_C];
    __shared__ __nv_bfloat16 BsH[64][RS_C], BsL[64][RS_C];

    int tid = threadIdx.x;
    int m0 = blockIdx.y * 64, n0 = blockIdx.x * 64;
    int lane = tid & 31, wid = tid >> 5;
    int gq = lane >> 2, tg = lane & 3;
    int mrow = (wid & 3) * 16;
    int nq = (wid >> 2) * 32;

    float acc[4][4];
#pragma unroll
    for (int a = 0; a < 4; a++)
#pragma unroll
        for (int b = 0; b < 4; b++) acc[a][b] = 0.f;

    for (int kt = 0; kt < K; kt += 64) {
#pragma unroll
        for (int f4 = tid; f4 < 512; f4 += 256) {
            int row = f4 >> 3, c = f4 & 7;
            *((float4*)&AsH[row][c * 8]) = *(const float4*)(Ah + (size_t)(m0 + row) * K + kt + c * 8);
            *((float4*)&AsL[row][c * 8]) = *(const float4*)(Al + (size_t)(m0 + row) * K + kt + c * 8);
            *((float4*)&BsH[row][c * 8]) = *(const float4*)(g_wbh + (size_t)(n0 + row) * K + kt + c * 8);
            *((float4*)&BsL[row][c * 8]) = *(const float4*)(g_wbl + (size_t)(n0 + row) * K + kt + c * 8);
        }
        __syncthreads();
#pragma unroll
        for (int kk = 0; kk < 64; kk += 16) {
            uint32_t ah0 = *(uint32_t*)&AsH[mrow + gq][kk + 2 * tg];
            uint32_t ah1 = *(uint32_t*)&AsH[mrow + gq + 8][kk + 2 * tg];
            uint32_t ah2 = *(uint32_t*)&AsH[mrow + gq][kk + 2 * tg + 8];
            uint32_t ah3 = *(uint32_t*)&AsH[mrow + gq + 8][kk + 2 * tg + 8];
            uint32_t al0 = *(uint32_t*)&AsL[mrow + gq][kk + 2 * tg];
            uint32_t al1 = *(uint32_t*)&AsL[mrow + gq + 8][kk + 2 * tg];
            uint32_t al2 = *(uint32_t*)&AsL[mrow + gq][kk + 2 * tg + 8];
            uint32_t al3 = *(uint32_t*)&AsL[mrow + gq + 8][kk + 2 * tg + 8];
#pragma unroll
            for (int nf = 0; nf < 4; nf++) {
                int n = nq + nf * 8 + gq;
                uint32_t bh0 = *(uint32_t*)&BsH[n][kk + 2 * tg];
                uint32_t bh1 = *(uint32_t*)&BsH[n][kk + 2 * tg + 8];
                uint32_t bl0 = *(uint32_t*)&BsL[n][kk + 2 * tg];
                uint32_t bl1 = *(uint32_t*)&BsL[n][kk + 2 * tg + 8];
                mma16816(acc[nf], ah0, ah1, ah2, ah3, bh0, bh1);
                mma16816(acc[nf], al0, al1, al2, al3, bh0, bh1);
                mma16816(acc[nf], ah0, ah1, ah2, ah3, bl0, bl1);
            }
        }
        __syncthreads();
    }

#pragma unroll
    for (int nf = 0; nf < 4; nf++) {
        int col = n0 + nq + nf * 8 + 2 * tg;
        float bs0 = bias1[col] + bias2[col];
        float bs1 = bias1[col + 1] + bias2[col + 1];
        int r0 = m0 + mrow + gq;
        g_xp[(size_t)r0 * GG + col] = acc[nf][0] + bs0;
        g_xp[(size_t)r0 * GG + col + 1] = acc[nf][1] + bs1;
        g_xp[(size_t)(r0 + 8) * GG + col] = acc[nf][2] + bs0;
        g_xp[(size_t)(r0 + 8) * GG + col + 1] = acc[nf][3] + bs1;
    }
}

// ---------------- persistent recurrence (bf16x3) ----------------
// 64 CTAs; CTA owns 16 h-cols (64 gate rows). W_hi resident SMEM; W_lo and
// h hi/lo planes streamed per 64-wide k-chunk with double-buffered cp.async.cg.
__global__ __launch_bounds__(256) void recur_kernel(const float* __restrict__ w_hh) {
    extern __shared__ unsigned char smem[];
    __nv_bfloat16* Ws = (__nv_bfloat16*)(smem + OFF_WS);
    __nv_bfloat16* HsH = (__nv_bfloat16*)(smem + OFF_HH0);   // 2 buffers of 64*RS_C
    __nv_bfloat16* HsL = (__nv_bfloat16*)(smem + OFF_HL0);
    __nv_bfloat16* WsL = (__nv_bfloat16*)(smem + OFF_WL0);
    float* Gs = (float*)(smem + OFF_GS);
    float* Cs = (float*)(smem + OFF_CS);

    int tid = threadIdx.x;
    int j0 = blockIdx.x * 16;

    // Preload W_hi slice: local row r = q*16+i -> global row q*HH + j0 + i
    for (int idx = tid; idx < 64 * 1024; idx += 256) {
        int r = idx >> 10, k = idx & 1023;
        int q = r >> 4, i = r & 15;
        Ws[r * RS_W + k] = __float2bfloat16(w_hh[(size_t)(q * HH + j0 + i) * HH + k]);
    }
    for (int idx = tid; idx < 1024; idx += 256) Cs[idx] = 0.f;
    __syncthreads();

    int lane = tid & 31, wid = tid >> 5;
    int gq = lane >> 2, tg = lane & 3;
    int mrow = (wid & 3) << 4;
    int nq = (wid >> 2) << 5;

    for (int t = 0; t < TT; t++) {
        const __nv_bfloat16* rbh = g_hbuf_h[(t + 1) & 1];
        const __nv_bfloat16* rbl = g_hbuf_l[(t + 1) & 1];
        __nv_bfloat16* wbh = g_hbuf_h[t & 1];
        __nv_bfloat16* wbl = g_hbuf_l[t & 1];

        float acc[4][4];
#pragma unroll
        for (int a = 0; a < 4; a++)
#pragma unroll
            for (int b = 0; b < 4; b++) acc[a][b] = 0.f;

        // issue chunk 0
        {
            int kc = 0;
#pragma unroll
            for (int s = tid; s < 1536; s += 256) {
                int which = s >> 9, r = (s >> 3) & 63, seg = s & 7;
                if (which == 0)
                    cp_async16(HsH + r * RS_C + seg * 8, rbh + (size_t)r * HH + kc + seg * 8);
                else if (which == 1)
                    cp_async16(HsL + r * RS_C + seg * 8, rbl + (size_t)r * HH + kc + seg * 8);
                else {
                    int q = r >> 4, i = r & 15;
                    cp_async16(WsL + r * RS_C + seg * 8,
                               g_whh_lo + (size_t)(q * HH + j0 + i) * HH + kc + seg * 8);
                }
            }
            CP_COMMIT();
        }

        for (int ci = 0; ci < NCH; ci++) {
            if (ci + 1 < NCH) {
                int kc = (ci + 1) * CH;
                int bo = ((ci + 1) & 1) * 64 * RS_C;
#pragma unroll
                for (int s = tid; s < 1536; s += 256) {
                    int which = s >> 9, r = (s >> 3) & 63, seg = s & 7;
                    if (which == 0)
                        cp_async16(HsH + bo + r * RS_C + seg * 8, rbh + (size_t)r * HH + kc + seg * 8);
                    else if (which == 1)
                        cp_async16(HsL + bo + r * RS_C + seg * 8, rbl + (size_t)r * HH + kc + seg * 8);
                    else {
                        int q = r >> 4, i = r & 15;
                        cp_async16(WsL + bo + r * RS_C + seg * 8,
                                   g_whh_lo + (size_t)(q * HH + j0 + i) * HH + kc + seg * 8);
                    }
                }
                CP_COMMIT();
                CP_WAIT(1);
            } else {
                CP_WAIT(0);
            }
            __syncthreads();

            int bo = (ci & 1) * 64 * RS_C;
            const __nv_bfloat16* hH = HsH + bo;
            const __nv_bfloat16* hL = HsL + bo;
            const __nv_bfloat16* wL = WsL + bo;
            int kcc = ci * CH;
#pragma unroll
            for (int kk = 0; kk < CH; kk += 16) {
                uint32_t ah0 = *(uint32_t*)&hH[(mrow + gq) * RS_C + kk + 2 * tg];
                uint32_t ah1 = *(uint32_t*)&hH[(mrow + gq + 8) * RS_C + kk + 2 * tg];
                uint32_t ah2 = *(uint32_t*)&hH[(mrow + gq) * RS_C + kk + 2 * tg + 8];
                uint32_t ah3 = *(uint32_t*)&hH[(mrow + gq + 8) * RS_C + kk + 2 * tg + 8];
                uint32_t al0 = *(uint32_t*)&hL[(mrow + gq) * RS_C + kk + 2 * tg];
                uint32_t al1 = *(uint32_t*)&hL[(mrow + gq + 8) * RS_C + kk + 2 * tg];
                uint32_t al2 = *(uint32_t*)&hL[(mrow + gq) * RS_C + kk + 2 * tg + 8];
                uint32_t al3 = *(uint32_t*)&hL[(mrow + gq + 8) * RS_C + kk + 2 * tg + 8];
                int kw = kcc + kk;
#pragma unroll
                for (int nf = 0; nf < 4; nf++) {
                    int n = nq + nf * 8 + gq;
                    uint32_t bh0 = *(uint32_t*)&Ws[n * RS_W + kw + 2 * tg];
                    uint32_t bh1 = *(uint32_t*)&Ws[n * RS_W + kw + 2 * tg + 8];
                    uint32_t bl0 = *(uint32_t*)&wL[n * RS_C + kk + 2 * tg];
                    uint32_t bl1 = *(uint32_t*)&wL[n * RS_C + kk + 2 * tg + 8];
                    mma16816(acc[nf], ah0, ah1, ah2, ah3, bh0, bh1);
                    mma16816(acc[nf], al0, al1, al2, al3, bh0, bh1);
                    mma16816(acc[nf], ah0, ah1, ah2, ah3, bl0, bl1);
                }
            }
            __syncthreads();
        }

        // gates -> SMEM to regroup (b, j)
#pragma unroll
        for (int nf = 0; nf < 4; nf++) {
            int col = nq + nf * 8 + 2 * tg;
            Gs[(mrow + gq) * RS_G + col] = acc[nf][0];
            Gs[(mrow + gq) * RS_G + col + 1] = acc[nf][1];
            Gs[(mrow + gq + 8) * RS_G + col] = acc[nf][2];
            Gs[(mrow + gq + 8) * RS_G + col + 1] = acc[nf][3];
        }
        __syncthreads();

        const float* xpt = g_xp + (size_t)t * BB * GG;
#pragma unroll
        for (int e = tid; e < 1024; e += 256) {
            int b = e >> 4, i = e & 15;
            float gi = Gs[b * RS_G + i]      + xpt[(size_t)b * GG + j0 + i];
            float gf = Gs[b * RS_G + 16 + i] + xpt[(size_t)b * GG + HH + j0 + i];
            float gg = Gs[b * RS_G + 32 + i] + xpt[(size_t)b * GG + 2 * HH + j0 + i];
            float go = Gs[b * RS_G + 48 + i] + xpt[(size_t)b * GG + 3 * HH + j0 + i];
            float si = sigmoid_f(gi);
            float sf = sigmoid_f(gf);
            float sg = tanh_f(gg);
            float so = sigmoid_f(go);
            float c = sf * Cs[e] + si * sg;
            Cs[e] = c;
            float h = so * tanh_f(c);
            __nv_bfloat16 hi, lo;
            split_bf16(h, hi, lo);
            size_t po = (size_t)b * HH + j0 + i;
            wbh[po] = hi;
            wbl[po] = lo;
            size_t so2 = ((size_t)t * BB + b) * HH + j0 + i;
            g_hseq_h[so2] = hi;
            g_hseq_l[so2] = lo;
        }
        __syncthreads();

        // grid-wide step barrier (64 CTAs, all resident)
        if (tid == 0) {
            __threadfence();
            atomicAdd(&g_arrive[t], 1u);
            while (*((volatile unsigned*)&g_arrive[t]) < 64u) {}
            __threadfence();
        }
        __syncthreads();
    }
}

// ---------------- final linear ----------------
__global__ void final_kernel(const float* __restrict__ w_lin,
                             const float* __restrict__ b_lin,
                             float* __restrict__ out) {
    int b = blockIdx.x;
    __shared__ float red[256];
    float s = 0.f;
    size_t base = ((size_t)(TT - 1) * BB + b) * HH;
    for (int i = threadIdx.x; i < HH; i += 256) {
        float h = __bfloat162float(g_hseq_h[base + i]) + __bfloat162float(g_hseq_l[base + i]);
        s += h * w_lin[i];
    }
    red[threadIdx.x] = s;
    __syncthreads();
    for (int st = 128; st > 0; st >>= 1) {
        if (threadIdx.x < st) red[threadIdx.x] += red[threadIdx.x + st];
        __syncthreads();
    }
    if (threadIdx.x == 0) out[b] = red[0] + b_lin[0];
}

// ---------------- launch ----------------
extern "C" void kernel_launch(void* const* d_in, const int* in_sizes, int n_in,
                              void* d_out, int out_size) {
    const float* x     = (const float*)d_in[0];
    const float* w_ih0 = (const float*)d_in[1];
    const float* w_hh0 = (const float*)d_in[2];
    const float* b_ih0 = (const float*)d_in[3];
    const float* b_hh0 = (const float*)d_in[4];
    const float* w_ih1 = (const float*)d_in[5];
    const float* w_hh1 = (const float*)d_in[6];
    const float* b_ih1 = (const float*)d_in[7];
    const float* b_hh1 = (const float*)d_in[8];
    const float* w_lin = (const float*)d_in[9];
    const float* b_lin = (const float*)d_in[10];
    float* out = (float*)d_out;

    cudaFuncSetAttribute(recur_kernel, cudaFuncAttributeMaxDynamicSharedMemorySize,
                         SMEM_RECUR);

    // layer 0
    prep_kernel<<<256, 256>>>();
    convert_x_kernel<<<2048, 256>>>(x);
    convert_wih_kernel<<<1024, 256>>>(w_ih0, GG * DD);
    convert_whh_lo_kernel<<<2048, 256>>>(w_hh0);
    gemm_kernel<<<dim3(64, 512), 256>>>(0, DD, b_ih0, b_hh0);
    recur_kernel<<<64, 256, SMEM_RECUR>>>(w_hh0);

    // layer 1
    prep_kernel<<<256, 256>>>();
    convert_wih_kernel<<<4096, 256>>>(w_ih1, GG * HH);
    gemm_kernel<<<dim3(64, 512), 256>>>(1, HH, b_ih1, b_hh1);
    convert_whh_lo_kernel<<<2048, 256>>>(w_hh1);
    recur_kernel<<<64, 256, SMEM_RECUR>>>(w_hh1);

    // output head
    final_kernel<<<64, 256>>>(w_lin, b_lin, out);
}

// round 8
// speedup vs baseline: 1.3898x; 1.3898x over previous
#include <cuda_runtime.h>
#include <cuda_bf16.h>
#include <cstdint>

#define BB 64      // batch
#define TT 512     // timesteps
#define DD 256     // input dim
#define HH 1024    // hidden
#define GG 4096    // 4*H

// ---------------- scratch (device-global; no allocs allowed) ----------------
__device__ __align__(16) __nv_bfloat16 g_A0h[(size_t)TT * BB * DD];   // x hi plane [t*B+b][D]
__device__ __align__(16) __nv_bfloat16 g_A0l[(size_t)TT * BB * DD];   // x lo plane
__device__ __align__(16) __nv_bfloat16 g_wbh[(size_t)GG * HH];        // w_ih hi
__device__ __align__(16) __nv_bfloat16 g_wbl[(size_t)GG * HH];        // w_ih lo
__device__ __align__(16) float         g_xp[(size_t)TT * BB * GG];    // projections + biases
__device__ __align__(16) __nv_bfloat16 g_hseq_h[(size_t)TT * BB * HH];
__device__ __align__(16) __nv_bfloat16 g_hseq_l[(size_t)TT * BB * HH];
__device__ __align__(16) __nv_bfloat16 g_hbuf_h[2][BB * HH];
__device__ __align__(16) __nv_bfloat16 g_hbuf_l[2][BB * HH];
__device__ unsigned g_arrive[TT];

#define NCTA 128     // recurrence CTAs (<=148, all resident)

// SMEM strides (word stride mod 32 == 4 -> conflict-free quad access)
#define RS_C 72      // chunk row stride (bf16)
#define RS_W2 1032   // resident W row stride (bf16): 516 words, 516%32=4
#define RS_G 36      // gate row stride (fp32)
#define NCH  16      // 1024/64 k-chunks
#define CH   64

// recurrence SMEM layout (bytes)
#define OFF2_WH 0                                   // 32*RS_W2*2 = 66048
#define OFF2_WL 66048                               // -> 132096
#define OFF2_HH 132096                              // 2 bufs * 64*RS_C*2 = 18432
#define OFF2_HL 150528                              // -> 168960
#define OFF2_PS 168960                              // 3 * 64*RS_G*4 = 27648
#define OFF2_GS 196608                              // 64*RS_G*4 = 9216
#define OFF2_CS 205824                              // 512*4 = 2048
#define SMEM_RECUR 207872

// gemm SMEM
// ---------------- helpers ----------------
__device__ __forceinline__ void mma16816(float* c, uint32_t a0, uint32_t a1,
                                         uint32_t a2, uint32_t a3,
                                         uint32_t b0, uint32_t b1) {
    asm volatile(
        "mma.sync.aligned.m16n8k16.row.col.f32.bf16.bf16.f32 "
        "{%0,%1,%2,%3}, {%4,%5,%6,%7}, {%8,%9}, {%0,%1,%2,%3};"
        : "+f"(c[0]), "+f"(c[1]), "+f"(c[2]), "+f"(c[3])
        : "r"(a0), "r"(a1), "r"(a2), "r"(a3), "r"(b0), "r"(b1));
}
__device__ __forceinline__ void cp_async16(void* s, const void* g) {
    uint32_t sa = (uint32_t)__cvta_generic_to_shared(s);
    asm volatile("cp.async.cg.shared.global [%0], [%1], 16;\n" ::"r"(sa), "l"(g));
}
#define CP_COMMIT() asm volatile("cp.async.commit_group;\n")
#define CP_WAIT(N)  asm volatile("cp.async.wait_group %0;\n" ::"n"(N))

__device__ __forceinline__ float sigmoid_f(float x) { return 1.f / (1.f + __expf(-x)); }
__device__ __forceinline__ float tanh_f(float x) { return 2.f / (1.f + __expf(-2.f * x)) - 1.f; }

__device__ __forceinline__ void split_bf16(float v, __nv_bfloat16& hi, __nv_bfloat16& lo) {
    hi = __float2bfloat16(v);
    lo = __float2bfloat16(v - __bfloat162float(hi));
}

// ---------------- prep ----------------
__global__ void prep_kernel() {
    int idx = blockIdx.x * blockDim.x + threadIdx.x;
    int nh = 2 * BB * HH;
    int total = TT + 2 * nh;
    for (int i = idx; i < total; i += gridDim.x * blockDim.x) {
        if (i < TT) g_arrive[i] = 0u;
        else if (i < TT + nh) ((__nv_bfloat16*)g_hbuf_h)[i - TT] = __float2bfloat16(0.f);
        else ((__nv_bfloat16*)g_hbuf_l)[i - TT - nh] = __float2bfloat16(0.f);
    }
}

// x[B][T][D] fp32 -> split planes [t*B+b][D]
__global__ void convert_x_kernel(const float* __restrict__ x) {
    size_t total = (size_t)BB * TT * DD;
    for (size_t i = (size_t)blockIdx.x * blockDim.x + threadIdx.x; i < total;
         i += (size_t)gridDim.x * blockDim.x) {
        int b = (int)(i / (TT * DD));
        int r = (int)(i % (TT * DD));
        int t = r / DD, d = r % DD;
        __nv_bfloat16 hi, lo;
        split_bf16(x[i], hi, lo);
        size_t o = ((size_t)t * BB + b) * DD + d;
        g_A0h[o] = hi;
        g_A0l[o] = lo;
    }
}

__global__ void convert_wih_kernel(const float* __restrict__ w, int n) {
    for (int i = blockIdx.x * blockDim.x + threadIdx.x; i < n; i += gridDim.x * blockDim.x) {
        __nv_bfloat16 hi, lo;
        split_bf16(w[i], hi, lo);
        g_wbh[i] = hi;
        g_wbl[i] = lo;
    }
}

// ---------------- projection GEMM (bf16x3): C = A.Wt + b1 + b2 ----------------
__global__ __launch_bounds__(256) void gemm_kernel(int layer, int K,
                                                   const float* __restrict__ bias1,
                                                   const float* __restrict__ bias2) {
    const __nv_bfloat16* Ah = (layer == 0) ? g_A0h : g_hseq_h;
    const __nv_bfloat16* Al = (layer == 0) ? g_A0l : g_hseq_l;
    __shared__ __nv_bfloat16 AsH[64][RS_C], AsL[64][RS_C];
    __shared__ __nv_bfloat16 BsH[64][RS_C], BsL[64][RS_C];

    int tid = threadIdx.x;
    int m0 = blockIdx.y * 64, n0 = blockIdx.x * 64;
    int lane = tid & 31, wid = tid >> 5;
    int gq = lane >> 2, tg = lane & 3;
    int mrow = (wid & 3) * 16;
    int nq = (wid >> 2) * 32;

    float acc[4][4];
#pragma unroll
    for (int a = 0; a < 4; a++)
#pragma unroll
        for (int b = 0; b < 4; b++) acc[a][b] = 0.f;

    for (int kt = 0; kt < K; kt += 64) {
#pragma unroll
        for (int f4 = tid; f4 < 512; f4 += 256) {
            int row = f4 >> 3, c = f4 & 7;
            *((float4*)&AsH[row][c * 8]) = *(const float4*)(Ah + (size_t)(m0 + row) * K + kt + c * 8);
            *((float4*)&AsL[row][c * 8]) = *(const float4*)(Al + (size_t)(m0 + row) * K + kt + c * 8);
            *((float4*)&BsH[row][c * 8]) = *(const float4*)(g_wbh + (size_t)(n0 + row) * K + kt + c * 8);
            *((float4*)&BsL[row][c * 8]) = *(const float4*)(g_wbl + (size_t)(n0 + row) * K + kt + c * 8);
        }
        __syncthreads();
#pragma unroll
        for (int kk = 0; kk < 64; kk += 16) {
            uint32_t ah0 = *(uint32_t*)&AsH[mrow + gq][kk + 2 * tg];
            uint32_t ah1 = *(uint32_t*)&AsH[mrow + gq + 8][kk + 2 * tg];
            uint32_t ah2 = *(uint32_t*)&AsH[mrow + gq][kk + 2 * tg + 8];
            uint32_t ah3 = *(uint32_t*)&AsH[mrow + gq + 8][kk + 2 * tg + 8];
            uint32_t al0 = *(uint32_t*)&AsL[mrow + gq][kk + 2 * tg];
            uint32_t al1 = *(uint32_t*)&AsL[mrow + gq + 8][kk + 2 * tg];
            uint32_t al2 = *(uint32_t*)&AsL[mrow + gq][kk + 2 * tg + 8];
            uint32_t al3 = *(uint32_t*)&AsL[mrow + gq + 8][kk + 2 * tg + 8];
#pragma unroll
            for (int nf = 0; nf < 4; nf++) {
                int n = nq + nf * 8 + gq;
                uint32_t bh0 = *(uint32_t*)&BsH[n][kk + 2 * tg];
                uint32_t bh1 = *(uint32_t*)&BsH[n][kk + 2 * tg + 8];
                uint32_t bl0 = *(uint32_t*)&BsL[n][kk + 2 * tg];
                uint32_t bl1 = *(uint32_t*)&BsL[n][kk + 2 * tg + 8];
                mma16816(acc[nf], ah0, ah1, ah2, ah3, bh0, bh1);
                mma16816(acc[nf], al0, al1, al2, al3, bh0, bh1);
                mma16816(acc[nf], ah0, ah1, ah2, ah3, bl0, bl1);
            }
        }
        __syncthreads();
    }

#pragma unroll
    for (int nf = 0; nf < 4; nf++) {
        int col = n0 + nq + nf * 8 + 2 * tg;
        float bs0 = bias1[col] + bias2[col];
        float bs1 = bias1[col + 1] + bias2[col + 1];
        int r0 = m0 + mrow + gq;
        g_xp[(size_t)r0 * GG + col] = acc[nf][0] + bs0;
        g_xp[(size_t)r0 * GG + col + 1] = acc[nf][1] + bs1;
        g_xp[(size_t)(r0 + 8) * GG + col] = acc[nf][2] + bs0;
        g_xp[(size_t)(r0 + 8) * GG + col + 1] = acc[nf][3] + bs1;
    }
}

// ---------------- persistent recurrence (bf16x3), 128 CTAs ----------------
// CTA owns 8 h-cols (32 gate rows: local row r = q*8+i -> global q*HH+j0+i).
// Both W planes SMEM-resident. h hi/lo streamed per 64-wide chunk (cp.async,
// double buffered). 8 warps = 4 k-groups x 2 m-warps, each warp m32 x n32,
// k-slice 16 within each chunk. Per-step 3-partial SMEM reduction.
__global__ __launch_bounds__(256, 1) void recur_kernel(const float* __restrict__ w_hh) {
    extern __shared__ unsigned char smem[];
    __nv_bfloat16* Wh = (__nv_bfloat16*)(smem + OFF2_WH);
    __nv_bfloat16* Wl = (__nv_bfloat16*)(smem + OFF2_WL);
    __nv_bfloat16* HsH = (__nv_bfloat16*)(smem + OFF2_HH);   // 2 bufs of 64*RS_C
    __nv_bfloat16* HsL = (__nv_bfloat16*)(smem + OFF2_HL);
    float* PS = (float*)(smem + OFF2_PS);                    // 3 partial sets
    float* Gs = (float*)(smem + OFF2_GS);
    float* Cs = (float*)(smem + OFF2_CS);

    int tid = threadIdx.x;
    int j0 = blockIdx.x * 8;

    // Preload resident W slice (both planes), split from fp32
    for (int idx = tid; idx < 32 * 1024; idx += 256) {
        int r = idx >> 10, k = idx & 1023;
        int q = r >> 3, i = r & 7;
        float v = w_hh[(size_t)(q * HH + j0 + i) * HH + k];
        __nv_bfloat16 hi, lo;
        split_bf16(v, hi, lo);
        Wh[r * RS_W2 + k] = hi;
        Wl[r * RS_W2 + k] = lo;
    }
    for (int idx = tid; idx < 512; idx += 256) Cs[idx] = 0.f;
    __syncthreads();

    int lane = tid & 31, wid = tid >> 5;
    int gq = lane >> 2, tg = lane & 3;
    int kg = wid >> 1;           // k-group 0..3 (k-slice kg*16 within each chunk)
    int mbase = (wid & 1) << 5;  // 0 or 32

    for (int t = 0; t < TT; t++) {
        const __nv_bfloat16* rbh = g_hbuf_h[(t + 1) & 1];
        const __nv_bfloat16* rbl = g_hbuf_l[(t + 1) & 1];
        __nv_bfloat16* wbh = g_hbuf_h[t & 1];
        __nv_bfloat16* wbl = g_hbuf_l[t & 1];

        float acc[2][4][4];
#pragma unroll
        for (int a = 0; a < 2; a++)
#pragma unroll
            for (int b = 0; b < 4; b++)
#pragma unroll
                for (int c = 0; c < 4; c++) acc[a][b][c] = 0.f;

        // issue chunk 0 (h hi + lo planes: 1024 cp.async16)
        {
#pragma unroll
            for (int s = tid; s < 1024; s += 256) {
                int plane = s >> 9, r = (s >> 3) & 63, seg = s & 7;
                if (plane == 0)
                    cp_async16(HsH + r * RS_C + seg * 8, rbh + (size_t)r * HH + seg * 8);
                else
                    cp_async16(HsL + r * RS_C + seg * 8, rbl + (size_t)r * HH + seg * 8);
            }
            CP_COMMIT();
        }

        for (int ci = 0; ci < NCH; ci++) {
            if (ci + 1 < NCH) {
                int kc = (ci + 1) * CH;
                int bo = ((ci + 1) & 1) * 64 * RS_C;
#pragma unroll
                for (int s = tid; s < 1024; s += 256) {
                    int plane = s >> 9, r = (s >> 3) & 63, seg = s & 7;
                    if (plane == 0)
                        cp_async16(HsH + bo + r * RS_C + seg * 8, rbh + (size_t)r * HH + kc + seg * 8);
                    else
                        cp_async16(HsL + bo + r * RS_C + seg * 8, rbl + (size_t)r * HH + kc + seg * 8);
                }
                CP_COMMIT();
                CP_WAIT(1);
            } else {
                CP_WAIT(0);
            }
            __syncthreads();

            int bo = (ci & 1) * 64 * RS_C;
            const __nv_bfloat16* hH = HsH + bo;
            const __nv_bfloat16* hL = HsL + bo;
            int kks = kg * 16;            // slice within chunk
            int kw = ci * CH + kks;       // global k for resident W

            uint32_t ah[2][4], al[2][4];
#pragma unroll
            for (int mf = 0; mf < 2; mf++) {
                int r0 = mbase + mf * 16 + gq;
                ah[mf][0] = *(uint32_t*)&hH[r0 * RS_C + kks + 2 * tg];
                ah[mf][1] = *(uint32_t*)&hH[(r0 + 8) * RS_C + kks + 2 * tg];
                ah[mf][2] = *(uint32_t*)&hH[r0 * RS_C + kks + 2 * tg + 8];
                ah[mf][3] = *(uint32_t*)&hH[(r0 + 8) * RS_C + kks + 2 * tg + 8];
                al[mf][0] = *(uint32_t*)&hL[r0 * RS_C + kks + 2 * tg];
                al[mf][1] = *(uint32_t*)&hL[(r0 + 8) * RS_C + kks + 2 * tg];
                al[mf][2] = *(uint32_t*)&hL[r0 * RS_C + kks + 2 * tg + 8];
                al[mf][3] = *(uint32_t*)&hL[(r0 + 8) * RS_C + kks + 2 * tg + 8];
            }
#pragma unroll
            for (int nf = 0; nf < 4; nf++) {
                int n = nf * 8 + gq;
                uint32_t bh0 = *(uint32_t*)&Wh[n * RS_W2 + kw + 2 * tg];
                uint32_t bh1 = *(uint32_t*)&Wh[n * RS_W2 + kw + 2 * tg + 8];
                uint32_t bl0 = *(uint32_t*)&Wl[n * RS_W2 + kw + 2 * tg];
                uint32_t bl1 = *(uint32_t*)&Wl[n * RS_W2 + kw + 2 * tg + 8];
#pragma unroll
                for (int mf = 0; mf < 2; mf++) {
                    mma16816(acc[mf][nf], ah[mf][0], ah[mf][1], ah[mf][2], ah[mf][3], bh0, bh1);
                    mma16816(acc[mf][nf], al[mf][0], al[mf][1], al[mf][2], al[mf][3], bh0, bh1);
                    mma16816(acc[mf][nf], ah[mf][0], ah[mf][1], ah[mf][2], ah[mf][3], bl0, bl1);
                }
            }
            __syncthreads();
        }

        // k-group reduction: groups 1..3 dump partials, group 0 combines
        if (kg) {
            float* P = PS + (kg - 1) * 64 * RS_G;
#pragma unroll
            for (int mf = 0; mf < 2; mf++) {
                int r0 = mbase + mf * 16 + gq;
#pragma unroll
                for (int nf = 0; nf < 4; nf++) {
                    int col = nf * 8 + 2 * tg;
                    P[r0 * RS_G + col] = acc[mf][nf][0];
                    P[r0 * RS_G + col + 1] = acc[mf][nf][1];
                    P[(r0 + 8) * RS_G + col] = acc[mf][nf][2];
                    P[(r0 + 8) * RS_G + col + 1] = acc[mf][nf][3];
                }
            }
        }
        __syncthreads();
        if (kg == 0) {
#pragma unroll
            for (int mf = 0; mf < 2; mf++) {
                int r0 = mbase + mf * 16 + gq;
#pragma unroll
                for (int nf = 0; nf < 4; nf++) {
                    int col = nf * 8 + 2 * tg;
                    float s0 = acc[mf][nf][0], s1 = acc[mf][nf][1];
                    float s2 = acc[mf][nf][2], s3 = acc[mf][nf][3];
#pragma unroll
                    for (int p = 0; p < 3; p++) {
                        const float* P = PS + p * 64 * RS_G;
                        s0 += P[r0 * RS_G + col];
                        s1 += P[r0 * RS_G + col + 1];
                        s2 += P[(r0 + 8) * RS_G + col];
                        s3 += P[(r0 + 8) * RS_G + col + 1];
                    }
                    Gs[r0 * RS_G + col] = s0;
                    Gs[r0 * RS_G + col + 1] = s1;
                    Gs[(r0 + 8) * RS_G + col] = s2;
                    Gs[(r0 + 8) * RS_G + col + 1] = s3;
                }
            }
        }
        __syncthreads();

        // cell update: 64 batches x 8 cols
        const float* xpt = g_xp + (size_t)t * BB * GG;
#pragma unroll
        for (int e = tid; e < 512; e += 256) {
            int b = e >> 3, i = e & 7;
            float gi = Gs[b * RS_G + i]      + xpt[(size_t)b * GG + j0 + i];
            float gf = Gs[b * RS_G + 8 + i]  + xpt[(size_t)b * GG + HH + j0 + i];
            float gg = Gs[b * RS_G + 16 + i] + xpt[(size_t)b * GG + 2 * HH + j0 + i];
            float go = Gs[b * RS_G + 24 + i] + xpt[(size_t)b * GG + 3 * HH + j0 + i];
            float si = sigmoid_f(gi);
            float sf = sigmoid_f(gf);
            float sg = tanh_f(gg);
            float so = sigmoid_f(go);
            float c = sf * Cs[e] + si * sg;
            Cs[e] = c;
            float h = so * tanh_f(c);
            __nv_bfloat16 hi, lo;
            split_bf16(h, hi, lo);
            size_t po = (size_t)b * HH + j0 + i;
            wbh[po] = hi;
            wbl[po] = lo;
            size_t so2 = ((size_t)t * BB + b) * HH + j0 + i;
            g_hseq_h[so2] = hi;
            g_hseq_l[so2] = lo;
        }
        __syncthreads();

        // grid-wide step barrier (NCTA CTAs, all resident)
        if (tid == 0) {
            __threadfence();
            atomicAdd(&g_arrive[t], 1u);
            while (*((volatile unsigned*)&g_arrive[t]) < NCTA) {}
            __threadfence();
        }
        __syncthreads();
    }
}

// ---------------- final linear ----------------
__global__ void final_kernel(const float* __restrict__ w_lin,
                             const float* __restrict__ b_lin,
                             float* __restrict__ out) {
    int b = blockIdx.x;
    __shared__ float red[256];
    float s = 0.f;
    size_t base = ((size_t)(TT - 1) * BB + b) * HH;
    for (int i = threadIdx.x; i < HH; i += 256) {
        float h = __bfloat162float(g_hseq_h[base + i]) + __bfloat162float(g_hseq_l[base + i]);
        s += h * w_lin[i];
    }
    red[threadIdx.x] = s;
    __syncthreads();
    for (int st = 128; st > 0; st >>= 1) {
        if (threadIdx.x < st) red[threadIdx.x] += red[threadIdx.x + st];
        __syncthreads();
    }
    if (threadIdx.x == 0) out[b] = red[0] + b_lin[0];
}

// ---------------- launch ----------------
extern "C" void kernel_launch(void* const* d_in, const int* in_sizes, int n_in,
                              void* d_out, int out_size) {
    const float* x     = (const float*)d_in[0];
    const float* w_ih0 = (const float*)d_in[1];
    const float* w_hh0 = (const float*)d_in[2];
    const float* b_ih0 = (const float*)d_in[3];
    const float* b_hh0 = (const float*)d_in[4];
    const float* w_ih1 = (const float*)d_in[5];
    const float* w_hh1 = (const float*)d_in[6];
    const float* b_ih1 = (const float*)d_in[7];
    const float* b_hh1 = (const float*)d_in[8];
    const float* w_lin = (const float*)d_in[9];
    const float* b_lin = (const float*)d_in[10];
    float* out = (float*)d_out;

    cudaFuncSetAttribute(recur_kernel, cudaFuncAttributeMaxDynamicSharedMemorySize,
                         SMEM_RECUR);

    // layer 0
    prep_kernel<<<256, 256>>>();
    convert_x_kernel<<<2048, 256>>>(x);
    convert_wih_kernel<<<1024, 256>>>(w_ih0, GG * DD);
    gemm_kernel<<<dim3(64, 512), 256>>>(0, DD, b_ih0, b_hh0);
    recur_kernel<<<NCTA, 256, SMEM_RECUR>>>(w_hh0);

    // layer 1
    prep_kernel<<<256, 256>>>();
    convert_wih_kernel<<<4096, 256>>>(w_ih1, GG * HH);
    gemm_kernel<<<dim3(64, 512), 256>>>(1, HH, b_ih1, b_hh1);
    recur_kernel<<<NCTA, 256, SMEM_RECUR>>>(w_hh1);

    // output head
    final_kernel<<<64, 256>>>(w_lin, b_lin, out);
}